// round 3
// baseline (speedup 1.0000x reference)
#include <cuda_runtime.h>
#include <cuda_bf16.h>
#include <math.h>

#define N_NODES 50000
#define N_EDGES 1600000
#define N_GRAPHS 512
#define FDIM 128
#define NHEADS 4

// Scratch (device globals — no allocation allowed)
__device__ __align__(16) float g_h[N_NODES * FDIM];     // transformed features this layer
__device__ __align__(16) float g_acc[N_NODES * FDIM];   // numerator accumulator
__device__ __align__(16) float g_x[N_NODES * FDIM];     // layer output / next layer input
__device__ __align__(16) float g_as[N_NODES * NHEADS];  // alpha_src per node/head
__device__ __align__(16) float g_ad[N_NODES * NHEADS];  // alpha_dst per node/head
__device__ __align__(16) float g_den[N_NODES * NHEADS]; // denominator accumulator
__device__ float g_cnt[N_GRAPHS];
__device__ int g_i64;  // 1 if index inputs are int64, 0 if int32

__device__ __forceinline__ float leaky(float v) { return v > 0.f ? v : 0.2f * v; }

__device__ __forceinline__ int load_idx(const void* p, int i) {
    return g_i64 ? (int)((const long long*)p)[i] : ((const int*)p)[i];
}

// ---------------------------------------------------------------------------
// K0: detect whether edge_index is int64 or int32.
// If int64 (values < 2^31), every odd 32-bit word of the first 64 entries is 0.
// If int32, 64 random node ids in [0, 50000) are essentially never all zero.
// ---------------------------------------------------------------------------
__global__ void k_detect(const int* __restrict__ ei_words) {
    if (threadIdx.x == 0 && blockIdx.x == 0) {
        int any = 0;
#pragma unroll
        for (int i = 1; i < 128; i += 2) any |= ei_words[i];
        g_i64 = (any == 0) ? 1 : 0;
    }
}

// ---------------------------------------------------------------------------
// K1: h = x @ W ; alpha_src/dst per head ; self-loop initialization of
//     accumulators (acc = w_self * h, den = w_self).  One warp per row.
// ---------------------------------------------------------------------------
__global__ void k_gemm(const float* __restrict__ xin_opt,
                       const float* __restrict__ W,
                       const float* __restrict__ a_s,
                       const float* __restrict__ a_d) {
    extern __shared__ float4 sW[];  // [128][32] float4 = 64 KB
    const float4* Wv = (const float4*)W;
    for (int i = threadIdx.x; i < FDIM * 32; i += blockDim.x) sW[i] = Wv[i];
    __syncthreads();

    const float* xin = xin_opt ? xin_opt : g_x;
    const int lane = threadIdx.x & 31;
    const int warp = (blockIdx.x * blockDim.x + threadIdx.x) >> 5;
    const int nwarps = (gridDim.x * blockDim.x) >> 5;

    // per-lane attention vector slice (lane covers channels lane*4..lane*4+3,
    // head = lane>>3, within-head offset = (lane&7)*4 → linear index = lane)
    const float4 asv = ((const float4*)a_s)[lane];
    const float4 adv = ((const float4*)a_d)[lane];

    for (int row = warp; row < N_NODES; row += nwarps) {
        float4 xv = ((const float4*)xin)[row * 32 + lane];
        float4 acc = make_float4(0.f, 0.f, 0.f, 0.f);
#pragma unroll
        for (int k = 0; k < FDIM; k++) {
            float xs;
            switch (k & 3) {
                case 0: xs = xv.x; break;
                case 1: xs = xv.y; break;
                case 2: xs = xv.z; break;
                default: xs = xv.w; break;
            }
            float xk = __shfl_sync(0xffffffffu, xs, k >> 2);
            float4 w4 = sW[k * 32 + lane];
            acc.x = fmaf(xk, w4.x, acc.x);
            acc.y = fmaf(xk, w4.y, acc.y);
            acc.z = fmaf(xk, w4.z, acc.z);
            acc.w = fmaf(xk, w4.w, acc.w);
        }
        ((float4*)g_h)[row * 32 + lane] = acc;

        // per-head dots with attention vectors, reduce over 8-lane head groups
        float ps = acc.x * asv.x + acc.y * asv.y + acc.z * asv.z + acc.w * asv.w;
        float pd = acc.x * adv.x + acc.y * adv.y + acc.z * adv.z + acc.w * adv.w;
#pragma unroll
        for (int o = 4; o; o >>= 1) {
            ps += __shfl_xor_sync(0xffffffffu, ps, o);
            pd += __shfl_xor_sync(0xffffffffu, pd, o);
        }
        // self-loop: e = leaky(as+ad); w = exp(e)  (no max-subtraction; |e| ~ O(10))
        float ws = __expf(leaky(ps + pd));
        ((float4*)g_acc)[row * 32 + lane] =
            make_float4(acc.x * ws, acc.y * ws, acc.z * ws, acc.w * ws);
        if ((lane & 7) == 0) {
            int hidx = row * NHEADS + (lane >> 3);
            g_den[hidx] = ws;
            g_as[hidx] = ps;
            g_ad[hidx] = pd;
        }
    }
}

// ---------------------------------------------------------------------------
// K2: edge scatter.  One warp per edge (grid-stride).
//     w = exp(leaky(as[src]+ad[dst])) per head; red.v4 numerator + denom.
// ---------------------------------------------------------------------------
__global__ void k_edge(const void* __restrict__ ei) {
    const int lane = threadIdx.x & 31;
    const int warp = (blockIdx.x * blockDim.x + threadIdx.x) >> 5;
    const int nwarps = (gridDim.x * blockDim.x) >> 5;
    for (int e = warp; e < N_EDGES; e += nwarps) {
        int s = load_idx(ei, e);
        int d = load_idx(ei, N_EDGES + e);
        if ((unsigned)s >= N_NODES || (unsigned)d >= N_NODES) continue;
        // lanes 0..3 hold the 4 head logits (replicated 8x across warp)
        float a = g_as[s * NHEADS + (lane & 3)];
        float b = g_ad[d * NHEADS + (lane & 3)];
        float wl = __expf(leaky(a + b));
        if (lane < 4) {
            float* pd = g_den + d * NHEADS + lane;
            asm volatile("red.global.add.f32 [%0], %1;" ::"l"(pd), "f"(wl)
                         : "memory");
        }
        float w = __shfl_sync(0xffffffffu, wl, lane >> 3);  // w for this lane's head
        float4 hv = ((const float4*)g_h)[s * 32 + lane];
        float* pa = g_acc + d * FDIM + lane * 4;
        asm volatile("red.global.add.v4.f32 [%0], {%1,%2,%3,%4};" ::"l"(pa),
                     "f"(hv.x * w), "f"(hv.y * w), "f"(hv.z * w), "f"(hv.w * w)
                     : "memory");
    }
}

// ---------------------------------------------------------------------------
// K3: finalize layer: x = elu(acc/den + bias)
// ---------------------------------------------------------------------------
__global__ void k_fin(const float* __restrict__ bias) {
    const int lane = threadIdx.x & 31;
    const int warp = (blockIdx.x * blockDim.x + threadIdx.x) >> 5;
    const int nwarps = (gridDim.x * blockDim.x) >> 5;
    float4 b4 = ((const float4*)bias)[lane];
    for (int row = warp; row < N_NODES; row += nwarps) {
        float den = g_den[row * NHEADS + (lane >> 3)] + 1e-16f;
        float inv = __fdividef(1.0f, den);
        float4 a = ((const float4*)g_acc)[row * 32 + lane];
        float4 r;
        r.x = a.x * inv + b4.x;
        r.y = a.y * inv + b4.y;
        r.z = a.z * inv + b4.z;
        r.w = a.w * inv + b4.w;
        r.x = r.x > 0.f ? r.x : expm1f(r.x);
        r.y = r.y > 0.f ? r.y : expm1f(r.y);
        r.z = r.z > 0.f ? r.z : expm1f(r.z);
        r.w = r.w > 0.f ? r.w : expm1f(r.w);
        ((float4*)g_x)[row * 32 + lane] = r;
    }
}

// ---------------------------------------------------------------------------
// Pooling
// ---------------------------------------------------------------------------
__global__ void k_zero(float* __restrict__ out) {
    int i = blockIdx.x * blockDim.x + threadIdx.x;
    if (i < N_GRAPHS * FDIM) out[i] = 0.f;
    if (i < N_GRAPHS) g_cnt[i] = 0.f;
}

__global__ void k_pool(const void* __restrict__ batch,
                       float* __restrict__ out) {
    const int lane = threadIdx.x & 31;
    const int warp = (blockIdx.x * blockDim.x + threadIdx.x) >> 5;
    const int nwarps = (gridDim.x * blockDim.x) >> 5;
    for (int row = warp; row < N_NODES; row += nwarps) {
        int g = load_idx(batch, row);
        if ((unsigned)g >= N_GRAPHS) continue;
        float4 v = ((const float4*)g_x)[row * 32 + lane];
        float* p = out + g * FDIM + lane * 4;
        asm volatile("red.global.add.v4.f32 [%0], {%1,%2,%3,%4};" ::"l"(p),
                     "f"(v.x), "f"(v.y), "f"(v.z), "f"(v.w)
                     : "memory");
        if (lane == 0) {
            float* pc = g_cnt + g;
            asm volatile("red.global.add.f32 [%0], %1;" ::"l"(pc), "f"(1.0f)
                         : "memory");
        }
    }
}

__global__ void k_div(float* __restrict__ out) {
    int i = blockIdx.x * blockDim.x + threadIdx.x;
    if (i < N_GRAPHS * FDIM) {
        float c = g_cnt[i >> 7];
        out[i] = out[i] / fmaxf(c, 1.0f);
    }
}

// ---------------------------------------------------------------------------
extern "C" void kernel_launch(void* const* d_in, const int* in_sizes, int n_in,
                              void* d_out, int out_size) {
    const float* x = (const float*)d_in[0];
    const float* Ws = (const float*)d_in[1];       // [3,128,128]
    const float* att_src = (const float*)d_in[2];  // [3,4,32]
    const float* att_dst = (const float*)d_in[3];  // [3,4,32]
    const float* biases = (const float*)d_in[4];   // [3,128]
    const void* ei = d_in[5];     // [2,E] int32 or int64 (detected on device)
    const void* batch = d_in[6];  // [N]
    float* out = (float*)d_out;

    cudaFuncSetAttribute(k_gemm, cudaFuncAttributeMaxDynamicSharedMemorySize,
                         65536);

    const int GEMM_BLOCKS = 444;   // 3 per SM (64 KB smem each)
    const int EDGE_BLOCKS = 1184;  // ~48 warps/SM for latency hiding
    const int NODE_BLOCKS = 1184;

    k_detect<<<1, 32>>>((const int*)ei);

    for (int l = 0; l < 3; l++) {
        const float* xin = (l == 0) ? x : nullptr;  // nullptr -> read g_x
        k_gemm<<<GEMM_BLOCKS, 256, 65536>>>(xin, Ws + l * FDIM * FDIM,
                                            att_src + l * NHEADS * 32,
                                            att_dst + l * NHEADS * 32);
        k_edge<<<EDGE_BLOCKS, 256>>>(ei);
        k_fin<<<NODE_BLOCKS, 256>>>(biases + l * FDIM);
    }
    k_zero<<<(N_GRAPHS * FDIM + 255) / 256, 256>>>(out);
    k_pool<<<NODE_BLOCKS, 256>>>(batch, out);
    k_div<<<(N_GRAPHS * FDIM + 255) / 256, 256>>>(out);
}

// round 4
// speedup vs baseline: 2.1784x; 2.1784x over previous
#include <cuda_runtime.h>
#include <cuda_bf16.h>
#include <math.h>
#include <stdint.h>

#define N_NODES 50000
#define N_EDGES 1600000
#define N_GRAPHS 512
#define FDIM 128
#define NHEADS 4
#define NBLK_SCAN 196  // ceil(50000/256)

// ---------------- scratch (device globals; no allocation allowed) ----------
__device__ __align__(16) float g_h[N_NODES * FDIM];
__device__ __align__(16) float g_x[N_NODES * FDIM];
__device__ __align__(16) float g_as[N_NODES * NHEADS];
__device__ __align__(16) float g_ad[N_NODES * NHEADS];
__device__ int g_deg[N_NODES];
__device__ int g_off[N_NODES + 1];
__device__ int g_cur[N_NODES];
__device__ int g_srcs[N_EDGES];
__device__ int g_bsum[256];
__device__ float g_cnt[N_GRAPHS];
__device__ int g_i64;

__device__ __forceinline__ float leaky(float v) { return v > 0.f ? v : 0.2f * v; }
__device__ __forceinline__ int load_idx(const void* p, int i) {
    return g_i64 ? (int)((const long long*)p)[i] : ((const int*)p)[i];
}

// ---------------------------------------------------------------------------
// K0: index dtype detection (int64 values < 2^31 -> odd words all zero)
// ---------------------------------------------------------------------------
__global__ void k_detect(const int* __restrict__ ei_words) {
    if (threadIdx.x == 0) {
        int any = 0;
#pragma unroll
        for (int i = 1; i < 128; i += 2) any |= ei_words[i];
        g_i64 = (any == 0) ? 1 : 0;
    }
}

// ---------------------------------------------------------------------------
// CSR build: zero degrees -> histogram -> scan -> scatter
// ---------------------------------------------------------------------------
__global__ void k_zero_deg() {
    int i = blockIdx.x * blockDim.x + threadIdx.x;
    if (i < N_NODES) g_deg[i] = 0;
}

__global__ void k_hist(const void* __restrict__ ei) {
    int e = blockIdx.x * blockDim.x + threadIdx.x;
    if (e < N_EDGES) {
        int d = load_idx(ei, N_EDGES + e);
        if ((unsigned)d < N_NODES) atomicAdd(&g_deg[d], 1);
    }
}

__global__ void k_scan1() {
    __shared__ int s[256];
    int t = threadIdx.x;
    int i = blockIdx.x * 256 + t;
    int v = (i < N_NODES) ? g_deg[i] : 0;
    s[t] = v;
    __syncthreads();
#pragma unroll
    for (int o = 1; o < 256; o <<= 1) {
        int x = s[t];
        if (t >= o) x += s[t - o];
        __syncthreads();
        s[t] = x;
        __syncthreads();
    }
    if (i < N_NODES) g_off[i + 1] = s[t];
    if (t == 255) g_bsum[blockIdx.x] = s[255];
}

__global__ void k_scan2() {
    __shared__ int s[256];
    int t = threadIdx.x;
    int v = (t < NBLK_SCAN) ? g_bsum[t] : 0;
    s[t] = v;
    __syncthreads();
#pragma unroll
    for (int o = 1; o < 256; o <<= 1) {
        int x = s[t];
        if (t >= o) x += s[t - o];
        __syncthreads();
        s[t] = x;
        __syncthreads();
    }
    if (t < NBLK_SCAN) g_bsum[t] = s[t] - v;  // exclusive
}

__global__ void k_scan3() {
    int i = blockIdx.x * blockDim.x + threadIdx.x;
    if (i < N_NODES) {
        int off = g_off[i + 1] + g_bsum[i >> 8];
        g_off[i + 1] = off;
        g_cur[i] = off - g_deg[i];  // segment start = cursor init
    }
    if (i == 0) g_off[0] = 0;
}

__global__ void k_scatter(const void* __restrict__ ei) {
    int e = blockIdx.x * blockDim.x + threadIdx.x;
    if (e < N_EDGES) {
        int s = load_idx(ei, e);
        int d = load_idx(ei, N_EDGES + e);
        if ((unsigned)s < N_NODES && (unsigned)d < N_NODES) {
            int pos = atomicAdd(&g_cur[d], 1);
            g_srcs[pos] = s;
        }
    }
}

// ---------------------------------------------------------------------------
// K1: tiled GEMM with packed f32x2 FMA.  64 rows x 128 cols per block.
//     Epilogue: write g_h, per-head alpha_src/alpha_dst.
// ---------------------------------------------------------------------------
#define XSTRIDE 68  // floats; keeps (272k + 32rs) 16B-aligned, conflict-free
#define GEMM_SMEM_BYTES (128 * 128 * 4 + 128 * XSTRIDE * 4)

__global__ void __launch_bounds__(256, 2)
k_gemm(const float* __restrict__ xin_opt, const float* __restrict__ W,
       const float* __restrict__ a_s, const float* __restrict__ a_d) {
    extern __shared__ float smem[];
    float* sW = smem;                 // [128][128]
    float* sX = smem + 128 * 128;     // [128][XSTRIDE] transposed x tile
    const float* xin = xin_opt ? xin_opt : g_x;
    const int tid = threadIdx.x;
    const int row0 = blockIdx.x * 64;

    // stage W (4096 float4, 16 per thread)
    {
        const float4* Wv = (const float4*)W;
        float4* sWv = (float4*)sW;
#pragma unroll
        for (int i = 0; i < 16; i++) sWv[tid + 256 * i] = Wv[tid + 256 * i];
    }
    // stage x transposed: sX[k][r] = x[row0+r][k]
#pragma unroll
    for (int i = 0; i < 8; i++) {
        int r = (tid & 31) + 32 * (i & 1);
        int k4 = (tid >> 5) + 8 * (i >> 1);
        int row = row0 + r;
        float4 v = (row < N_NODES) ? ((const float4*)xin)[row * 32 + k4]
                                   : make_float4(0.f, 0.f, 0.f, 0.f);
        sX[(k4 * 4 + 0) * XSTRIDE + r] = v.x;
        sX[(k4 * 4 + 1) * XSTRIDE + r] = v.y;
        sX[(k4 * 4 + 2) * XSTRIDE + r] = v.z;
        sX[(k4 * 4 + 3) * XSTRIDE + r] = v.w;
    }
    __syncthreads();

    const int lane = tid & 31;  // col slot: cols lane*4 .. +4
    const int rs = tid >> 5;    // row slot (warp): rows rs*8 .. +8

    uint32_t sbase = (uint32_t)__cvta_generic_to_shared(smem);
    uint32_t wA = sbase + lane * 16;                       // + k*512
    uint32_t xA = sbase + 128 * 128 * 4 + rs * 32;         // + k*XSTRIDE*4

    unsigned long long acc[4][4];
#pragma unroll
    for (int p = 0; p < 4; p++)
#pragma unroll
        for (int c = 0; c < 4; c++) acc[p][c] = 0ull;

#pragma unroll 8
    for (int k = 0; k < 128; k++) {
        float w0, w1, w2, w3;
        asm("ld.shared.v4.f32 {%0,%1,%2,%3}, [%4];"
            : "=f"(w0), "=f"(w1), "=f"(w2), "=f"(w3)
            : "r"(wA + (uint32_t)(k * 512)));
        unsigned long long wd[4];
        asm("mov.b64 %0, {%1,%1};" : "=l"(wd[0]) : "f"(w0));
        asm("mov.b64 %0, {%1,%1};" : "=l"(wd[1]) : "f"(w1));
        asm("mov.b64 %0, {%1,%1};" : "=l"(wd[2]) : "f"(w2));
        asm("mov.b64 %0, {%1,%1};" : "=l"(wd[3]) : "f"(w3));
        unsigned long long xp[4];
        asm("ld.shared.v2.u64 {%0,%1}, [%2];"
            : "=l"(xp[0]), "=l"(xp[1]) : "r"(xA + (uint32_t)(k * XSTRIDE * 4)));
        asm("ld.shared.v2.u64 {%0,%1}, [%2];"
            : "=l"(xp[2]), "=l"(xp[3]) : "r"(xA + (uint32_t)(k * XSTRIDE * 4 + 16)));
#pragma unroll
        for (int p = 0; p < 4; p++)
#pragma unroll
            for (int c = 0; c < 4; c++)
                asm("fma.rn.f32x2 %0, %1, %2, %0;"
                    : "+l"(acc[p][c]) : "l"(xp[p]), "l"(wd[c]));
    }

    // unpack: rows 2p (lo) and 2p+1 (hi)
    float vals[8][4];
#pragma unroll
    for (int p = 0; p < 4; p++)
#pragma unroll
        for (int c = 0; c < 4; c++) {
            float lo, hi;
            asm("mov.b64 {%0,%1}, %2;" : "=f"(lo), "=f"(hi) : "l"(acc[p][c]));
            vals[2 * p][c] = lo;
            vals[2 * p + 1][c] = hi;
        }

    const float4 asv = ((const float4*)a_s)[lane];
    const float4 adv = ((const float4*)a_d)[lane];
#pragma unroll
    for (int r = 0; r < 8; r++) {
        int row = row0 + rs * 8 + r;
        if (row >= N_NODES) break;
        float4 h = make_float4(vals[r][0], vals[r][1], vals[r][2], vals[r][3]);
        ((float4*)g_h)[row * 32 + lane] = h;
        float ps = h.x * asv.x + h.y * asv.y + h.z * asv.z + h.w * asv.w;
        float pd = h.x * adv.x + h.y * adv.y + h.z * adv.z + h.w * adv.w;
#pragma unroll
        for (int o = 4; o; o >>= 1) {
            ps += __shfl_xor_sync(0xffffffffu, ps, o);
            pd += __shfl_xor_sync(0xffffffffu, pd, o);
        }
        if ((lane & 7) == 0) {
            g_as[row * NHEADS + (lane >> 3)] = ps;
            g_ad[row * NHEADS + (lane >> 3)] = pd;
        }
    }
}

// ---------------------------------------------------------------------------
// K2: gather-based GAT aggregation + finalize.  One warp per dst node.
//     acc/den in registers (self-loop folded in), x = elu(acc/den + bias).
// ---------------------------------------------------------------------------
__global__ void __launch_bounds__(256) k_gat(const float* __restrict__ bias) {
    const int lane = threadIdx.x & 31;
    const int head = lane >> 3;
    const int h4 = lane & 3;
    const int warp = (blockIdx.x * blockDim.x + threadIdx.x) >> 5;
    const int nwarps = (gridDim.x * blockDim.x) >> 5;
    const float4 b4 = ((const float4*)bias)[lane];

    for (int row = warp; row < N_NODES; row += nwarps) {
        float ad_h = g_ad[row * NHEADS + h4];
        float as_self = g_as[row * NHEADS + h4];
        float wself = __expf(leaky(as_self + ad_h));
        float denp = (lane < 4) ? wself : 0.f;

        // self-loop init (wself in this lane corresponds to head h4; we need
        // the weight for this lane's *feature* head -> shuffle from lane=head)
        float ws = __shfl_sync(0xffffffffu, wself, head);
        float4 hs = ((const float4*)g_h)[row * 32 + lane];
        float4 acc = make_float4(ws * hs.x, ws * hs.y, ws * hs.z, ws * hs.w);

        int start = g_off[row];
        int end = g_off[row + 1];
        for (int base = start; base < end; base += 8) {
            int idx = base + (lane >> 2);
            bool valid = idx < end;
            int s = valid ? g_srcs[idx] : 0;
            float wl = valid ? __expf(leaky(g_as[s * NHEADS + h4] + ad_h)) : 0.f;
            denp += wl;
#pragma unroll
            for (int e = 0; e < 8; e++) {
                float w = __shfl_sync(0xffffffffu, wl, e * 4 + head);
                int se = __shfl_sync(0xffffffffu, s, e * 4);
                if (w != 0.f) {  // warp-uniform in practice
                    float4 hv = ((const float4*)g_h)[se * 32 + lane];
                    acc.x = fmaf(w, hv.x, acc.x);
                    acc.y = fmaf(w, hv.y, acc.y);
                    acc.z = fmaf(w, hv.z, acc.z);
                    acc.w = fmaf(w, hv.w, acc.w);
                }
            }
        }
        // reduce denp over lanes sharing same h4 (xor 4,8,16)
#pragma unroll
        for (int o = 4; o < 32; o <<= 1)
            denp += __shfl_xor_sync(0xffffffffu, denp, o);
        float den = __shfl_sync(0xffffffffu, denp, head) + 1e-16f;
        float inv = __fdividef(1.0f, den);
        float4 r;
        r.x = acc.x * inv + b4.x;
        r.y = acc.y * inv + b4.y;
        r.z = acc.z * inv + b4.z;
        r.w = acc.w * inv + b4.w;
        r.x = r.x > 0.f ? r.x : expm1f(r.x);
        r.y = r.y > 0.f ? r.y : expm1f(r.y);
        r.z = r.z > 0.f ? r.z : expm1f(r.z);
        r.w = r.w > 0.f ? r.w : expm1f(r.w);
        ((float4*)g_x)[row * 32 + lane] = r;
    }
}

// ---------------------------------------------------------------------------
// Pooling
// ---------------------------------------------------------------------------
__global__ void k_zero(float* __restrict__ out) {
    int i = blockIdx.x * blockDim.x + threadIdx.x;
    if (i < N_GRAPHS * FDIM) out[i] = 0.f;
    if (i < N_GRAPHS) g_cnt[i] = 0.f;
}

__global__ void k_pool(const void* __restrict__ batch, float* __restrict__ out) {
    const int lane = threadIdx.x & 31;
    const int warp = (blockIdx.x * blockDim.x + threadIdx.x) >> 5;
    const int nwarps = (gridDim.x * blockDim.x) >> 5;
    for (int row = warp; row < N_NODES; row += nwarps) {
        int g = load_idx(batch, row);
        if ((unsigned)g >= N_GRAPHS) continue;
        float4 v = ((const float4*)g_x)[row * 32 + lane];
        float* p = out + g * FDIM + lane * 4;
        asm volatile("red.global.add.v4.f32 [%0], {%1,%2,%3,%4};" ::"l"(p),
                     "f"(v.x), "f"(v.y), "f"(v.z), "f"(v.w)
                     : "memory");
        if (lane == 0) {
            float* pc = g_cnt + g;
            asm volatile("red.global.add.f32 [%0], %1;" ::"l"(pc), "f"(1.0f)
                         : "memory");
        }
    }
}

__global__ void k_div(float* __restrict__ out) {
    int i = blockIdx.x * blockDim.x + threadIdx.x;
    if (i < N_GRAPHS * FDIM) {
        float c = g_cnt[i >> 7];
        out[i] = out[i] / fmaxf(c, 1.0f);
    }
}

// ---------------------------------------------------------------------------
extern "C" void kernel_launch(void* const* d_in, const int* in_sizes, int n_in,
                              void* d_out, int out_size) {
    const float* x = (const float*)d_in[0];
    const float* Ws = (const float*)d_in[1];
    const float* att_src = (const float*)d_in[2];
    const float* att_dst = (const float*)d_in[3];
    const float* biases = (const float*)d_in[4];
    const void* ei = d_in[5];
    const void* batch = d_in[6];
    float* out = (float*)d_out;

    cudaFuncSetAttribute(k_gemm, cudaFuncAttributeMaxDynamicSharedMemorySize,
                         GEMM_SMEM_BYTES);

    const int EBLK = (N_EDGES + 255) / 256;   // 6250
    const int NODEBLK = (N_NODES + 255) / 256;
    const int GATBLK = (N_NODES + 7) / 8;     // 1 warp per node

    k_detect<<<1, 32>>>((const int*)ei);
    k_zero_deg<<<NODEBLK, 256>>>();
    k_hist<<<EBLK, 256>>>(ei);
    k_scan1<<<NBLK_SCAN, 256>>>();
    k_scan2<<<1, 256>>>();
    k_scan3<<<NBLK_SCAN, 256>>>();
    k_scatter<<<EBLK, 256>>>(ei);

    for (int l = 0; l < 3; l++) {
        const float* xin = (l == 0) ? x : nullptr;
        k_gemm<<<(N_NODES + 63) / 64, 256, GEMM_SMEM_BYTES>>>(
            xin, Ws + l * FDIM * FDIM, att_src + l * NHEADS * 32,
            att_dst + l * NHEADS * 32);
        k_gat<<<GATBLK, 256>>>(biases + l * FDIM);
    }
    k_zero<<<(N_GRAPHS * FDIM + 255) / 256, 256>>>(out);
    k_pool<<<1184, 256>>>(batch, out);
    k_div<<<(N_GRAPHS * FDIM + 255) / 256, 256>>>(out);
}